// round 3
// baseline (speedup 1.0000x reference)
#include <cuda_runtime.h>
#include <math.h>

#define BDIM 2
#define TSEQ 2048
#define DMODEL 1024
#define NHEADS 16
#define DK 64
#define MTOK (BDIM * TSEQ)   // 4096

// -------- scratch (device globals; no allocation allowed) --------
__device__ float g_Q[MTOK * DMODEL];
__device__ float g_K[MTOK * DMODEL];
__device__ float g_V[MTOK * DMODEL];
__device__ float g_ctx[MTOK * DMODEL];

// ============================================================================
// GEMM: Y[m,n] = sum_k A[m,k] * W[n,k] + bias[n]
// BM=BN=128, BK=8, 256 threads, 8x8 per-thread register tile.
// ============================================================================
__global__ __launch_bounds__(256)
void gemm_bias_kernel(const float* __restrict__ A, const float* __restrict__ W,
                      const float* __restrict__ bias, float* __restrict__ Y,
                      int M, int N, int K)
{
    __shared__ __align__(16) float As[8][128];
    __shared__ __align__(16) float Bs[8][128];

    const int tid = threadIdx.x;
    const int m0 = blockIdx.y * 128;
    const int n0 = blockIdx.x * 128;

    const int lm = tid >> 1;          // 0..127
    const int lk = (tid & 1) * 4;     // 0 or 4
    const int tm = (tid >> 4) * 8;    // 0..120
    const int tn = (tid & 15) * 8;    // 0..120

    float acc[8][8];
#pragma unroll
    for (int i = 0; i < 8; ++i)
#pragma unroll
        for (int j = 0; j < 8; ++j) acc[i][j] = 0.f;

    const float* aptr = A + (size_t)(m0 + lm) * K + lk;
    const float* wptr = W + (size_t)(n0 + lm) * K + lk;

    for (int k0 = 0; k0 < K; k0 += 8) {
        float4 av = *(const float4*)(aptr + k0);
        float4 bv = *(const float4*)(wptr + k0);
        __syncthreads();
        As[lk + 0][lm] = av.x; As[lk + 1][lm] = av.y;
        As[lk + 2][lm] = av.z; As[lk + 3][lm] = av.w;
        Bs[lk + 0][lm] = bv.x; Bs[lk + 1][lm] = bv.y;
        Bs[lk + 2][lm] = bv.z; Bs[lk + 3][lm] = bv.w;
        __syncthreads();

#pragma unroll
        for (int k = 0; k < 8; ++k) {
            float4 a0 = *(const float4*)&As[k][tm];
            float4 a1 = *(const float4*)&As[k][tm + 4];
            float4 b0 = *(const float4*)&Bs[k][tn];
            float4 b1 = *(const float4*)&Bs[k][tn + 4];
            float a[8] = {a0.x, a0.y, a0.z, a0.w, a1.x, a1.y, a1.z, a1.w};
            float b[8] = {b0.x, b0.y, b0.z, b0.w, b1.x, b1.y, b1.z, b1.w};
#pragma unroll
            for (int i = 0; i < 8; ++i)
#pragma unroll
                for (int j = 0; j < 8; ++j) acc[i][j] += a[i] * b[j];
        }
    }

    float4 bias0 = *(const float4*)&bias[n0 + tn];
    float4 bias1 = *(const float4*)&bias[n0 + tn + 4];
#pragma unroll
    for (int i = 0; i < 8; ++i) {
        float* yrow = Y + (size_t)(m0 + tm + i) * N + n0 + tn;
        float4 r0 = make_float4(acc[i][0] + bias0.x, acc[i][1] + bias0.y,
                                acc[i][2] + bias0.z, acc[i][3] + bias0.w);
        float4 r1 = make_float4(acc[i][4] + bias1.x, acc[i][5] + bias1.y,
                                acc[i][6] + bias1.z, acc[i][7] + bias1.w);
        *(float4*)(yrow)     = r0;
        *(float4*)(yrow + 4) = r1;
    }
}

// ============================================================================
// Causal flash attention (fp32).
// Block: 128 threads = 128 query rows. K/V staged in 32x64 smem tiles.
// q row and o accumulator live in registers. Online softmax.
// ============================================================================
#define AQ 128
#define AK 32

__global__ __launch_bounds__(128)
void attn_kernel(const float* __restrict__ Q, const float* __restrict__ K,
                 const float* __restrict__ V, float* __restrict__ ctx)
{
    __shared__ __align__(16) float Ks[AK][DK];
    __shared__ __align__(16) float Vs[AK][DK];

    const int t  = threadIdx.x;
    const int bq = blockIdx.x;       // query tile
    const int h  = blockIdx.y;
    const int b  = blockIdx.z;
    const int qg = bq * AQ + t;      // this thread's global query index
    const size_t base = ((size_t)b * TSEQ) * DMODEL + (size_t)h * DK;

    // load q row (scaled by 1/sqrt(dk) = 0.125)
    float4 q4[DK / 4];
    {
        const float4* qp = (const float4*)(Q + base + (size_t)qg * DMODEL);
#pragma unroll
        for (int i = 0; i < DK / 4; ++i) {
            float4 v = qp[i];
            v.x *= 0.125f; v.y *= 0.125f; v.z *= 0.125f; v.w *= 0.125f;
            q4[i] = v;
        }
    }

    float4 o4[DK / 4];
#pragma unroll
    for (int i = 0; i < DK / 4; ++i) o4[i] = make_float4(0.f, 0.f, 0.f, 0.f);
    float mrun = -1e30f, lrun = 0.f;

    const int ntiles = bq * (AQ / AK) + (AQ / AK);   // causal: up to block's last query

    for (int tile = 0; tile < ntiles; ++tile) {
        const int k0 = tile * AK;
        __syncthreads();
        // load 32x64 K and V tiles (512 float4 each, 128 threads x 4)
#pragma unroll
        for (int it = 0; it < 4; ++it) {
            int idx = it * 128 + t;        // 0..511
            int r = idx >> 4;              // row 0..31
            int c = (idx & 15) * 4;        // col
            *(float4*)&Ks[r][c] = *(const float4*)(K + base + (size_t)(k0 + r) * DMODEL + c);
            *(float4*)&Vs[r][c] = *(const float4*)(V + base + (size_t)(k0 + r) * DMODEL + c);
        }
        __syncthreads();

        float s[AK];
        float tmax = -1e30f;
#pragma unroll
        for (int j = 0; j < AK; ++j) {
            float acc = 0.f;
#pragma unroll
            for (int i = 0; i < DK / 4; ++i) {
                float4 kv = *(const float4*)&Ks[j][i * 4];
                acc += q4[i].x * kv.x + q4[i].y * kv.y
                     + q4[i].z * kv.z + q4[i].w * kv.w;
            }
            s[j] = (k0 + j <= qg) ? acc : -1e30f;
            tmax = fmaxf(tmax, s[j]);
        }

        float mnew = fmaxf(mrun, tmax);
        float corr = __expf(mrun - mnew);
        lrun *= corr;
#pragma unroll
        for (int i = 0; i < DK / 4; ++i) {
            o4[i].x *= corr; o4[i].y *= corr; o4[i].z *= corr; o4[i].w *= corr;
        }
#pragma unroll
        for (int j = 0; j < AK; ++j) {
            float p = __expf(s[j] - mnew);
            lrun += p;
#pragma unroll
            for (int i = 0; i < DK / 4; ++i) {
                float4 vv = *(const float4*)&Vs[j][i * 4];
                o4[i].x += p * vv.x; o4[i].y += p * vv.y;
                o4[i].z += p * vv.z; o4[i].w += p * vv.w;
            }
        }
        mrun = mnew;
    }

    const float inv = 1.f / lrun;
    float4* op = (float4*)(ctx + base + (size_t)qg * DMODEL);
#pragma unroll
    for (int i = 0; i < DK / 4; ++i) {
        o4[i].x *= inv; o4[i].y *= inv; o4[i].z *= inv; o4[i].w *= inv;
        op[i] = o4[i];
    }
}

// ============================================================================
// launch
// ============================================================================
extern "C" void kernel_launch(void* const* d_in, const int* in_sizes, int n_in,
                              void* d_out, int out_size)
{
    const float* x  = (const float*)d_in[0];
    const float* Wq = (const float*)d_in[1];
    const float* bq = (const float*)d_in[2];
    const float* Wk = (const float*)d_in[3];
    const float* bk = (const float*)d_in[4];
    const float* Wv = (const float*)d_in[5];
    const float* bv = (const float*)d_in[6];
    const float* Wo = (const float*)d_in[7];
    const float* bo = (const float*)d_in[8];
    float* out = (float*)d_out;

    float *qp, *kp, *vp, *cp;
    cudaGetSymbolAddress((void**)&qp, g_Q);
    cudaGetSymbolAddress((void**)&kp, g_K);
    cudaGetSymbolAddress((void**)&vp, g_V);
    cudaGetSymbolAddress((void**)&cp, g_ctx);

    dim3 ggrid(DMODEL / 128, MTOK / 128);   // (8, 32)
    dim3 gblk(256);

    gemm_bias_kernel<<<ggrid, gblk>>>(x, Wq, bq, qp, MTOK, DMODEL, DMODEL);
    gemm_bias_kernel<<<ggrid, gblk>>>(x, Wk, bk, kp, MTOK, DMODEL, DMODEL);
    gemm_bias_kernel<<<ggrid, gblk>>>(x, Wv, bv, vp, MTOK, DMODEL, DMODEL);

    dim3 agrid(TSEQ / AQ, NHEADS, BDIM);    // (16, 16, 2)
    attn_kernel<<<agrid, 128>>>(qp, kp, vp, cp);

    gemm_bias_kernel<<<ggrid, gblk>>>(cp, Wo, bo, out, MTOK, DMODEL, DMODEL);
}

// round 6
// speedup vs baseline: 1.3104x; 1.3104x over previous
#include <cuda_runtime.h>
#include <cstdint>
#include <math.h>

#define BDIM 2
#define TSEQ 2048
#define DMODEL 1024
#define NHEADS 16
#define DK 64
#define MTOK (BDIM * TSEQ)   // 4096

// -------- scratch (device globals; no allocation allowed) --------
__device__ float g_Q[MTOK * DMODEL];
__device__ float g_K[MTOK * DMODEL];
__device__ float g_V[MTOK * DMODEL];
__device__ float g_ctx[MTOK * DMODEL];

// ============================================================================
// helpers
// ============================================================================
__device__ __forceinline__ uint32_t smem_u32(const void* p) {
    uint32_t a;
    asm("{ .reg .u64 t; cvta.to.shared.u64 t, %1; cvt.u32.u64 %0, t; }" : "=r"(a) : "l"(p));
    return a;
}

__device__ __forceinline__ uint32_t f2tf32(float f) {
    uint32_t r;
    asm("cvt.rna.tf32.f32 %0, %1;" : "=r"(r) : "f"(f));
    return r;
}

__device__ __forceinline__ void mma_tf32(float* d, const uint32_t* a,
                                         uint32_t b0, uint32_t b1) {
    asm volatile(
        "mma.sync.aligned.m16n8k8.row.col.f32.tf32.tf32.f32 "
        "{%0,%1,%2,%3}, {%4,%5,%6,%7}, {%8,%9}, {%0,%1,%2,%3};"
        : "+f"(d[0]), "+f"(d[1]), "+f"(d[2]), "+f"(d[3])
        : "r"(a[0]), "r"(a[1]), "r"(a[2]), "r"(a[3]), "r"(b0), "r"(b1));
}

#define CP_ASYNC16(dst, src) \
    asm volatile("cp.async.cg.shared.global [%0], [%1], 16;" \
                 :: "r"((uint32_t)(dst)), "l"(src) : "memory")
#define CP_COMMIT() asm volatile("cp.async.commit_group;" ::: "memory")
#define CP_WAIT1()  asm volatile("cp.async.wait_group 1;" ::: "memory")
#define CP_WAIT0()  asm volatile("cp.async.wait_group 0;" ::: "memory")

// ============================================================================
// tf32 mma.sync GEMM: Y[m,n] = sum_k A[m,k]*W[n,k] + bias[n]
// CTA 128x128, BK=32, 256 thr (8 warps, 4x2), warp tile 32x64.
// Smem [128][36] (pad 4 -> conflict-free fragment LDS), cp.async double buffer.
// blockIdx.z selects (W, bias, Y).
// ============================================================================
#define GBK 32
#define NCHUNK (DMODEL / GBK)      // 32
#define SROW 36                    // 32 + 4 pad (floats)
#define TILE_F (128 * SROW)        // floats per tile buffer
#define GEMM_SMEM (4 * TILE_F * 4) // 73728 bytes

__global__ __launch_bounds__(256)
void gemm_tc_kernel(const float* __restrict__ A,
                    const float* __restrict__ W0, const float* __restrict__ W1,
                    const float* __restrict__ W2,
                    const float* __restrict__ b0, const float* __restrict__ b1,
                    const float* __restrict__ b2,
                    float* __restrict__ Y0, float* __restrict__ Y1,
                    float* __restrict__ Y2)
{
    extern __shared__ float smem[];
    float* As0 = smem;
    float* Ws0 = As0 + TILE_F;
    float* As1 = Ws0 + TILE_F;
    float* Ws1 = As1 + TILE_F;

    const float* W = W0; const float* bias = b0; float* Y = Y0;
    if (blockIdx.z == 1) { W = W1; bias = b1; Y = Y1; }
    else if (blockIdx.z == 2) { W = W2; bias = b2; Y = Y2; }

    const int tid  = threadIdx.x;
    const int wid  = tid >> 5;
    const int lane = tid & 31;
    const int m0 = blockIdx.y * 128;
    const int n0 = blockIdx.x * 128;

    const int m_warp = (wid & 3) * 32;     // warp M offset in CTA tile
    const int n_warp = (wid >> 2) * 64;    // warp N offset
    const int c4 = lane & 3;
    const int g8 = lane >> 2;

    // global load mapping: thread covers row (tid>>1), k-half (tid&1)*16
    const int rowL  = tid >> 1;
    const int khalf = (tid & 1) * 16;

    const float* Abase = A + (size_t)(m0 + rowL) * DMODEL + khalf;
    const float* Wbase = W + (size_t)(n0 + rowL) * DMODEL + khalf;
    const uint32_t sAoff = (uint32_t)(rowL * SROW + khalf) * 4u;
    const uint32_t sA0 = smem_u32(As0) + sAoff;
    const uint32_t sW0 = smem_u32(Ws0) + sAoff;
    const uint32_t sA1 = smem_u32(As1) + sAoff;
    const uint32_t sW1 = smem_u32(Ws1) + sAoff;

#define LOAD_CHUNK(c) do {                                                    \
    uint32_t _da = ((c) & 1) ? sA1 : sA0;                                     \
    uint32_t _dw = ((c) & 1) ? sW1 : sW0;                                     \
    const float* _ga = Abase + (c) * GBK;                                     \
    const float* _gw = Wbase + (c) * GBK;                                     \
    CP_ASYNC16(_da,      _ga);      CP_ASYNC16(_da + 16, _ga + 4);            \
    CP_ASYNC16(_da + 32, _ga + 8);  CP_ASYNC16(_da + 48, _ga + 12);           \
    CP_ASYNC16(_dw,      _gw);      CP_ASYNC16(_dw + 16, _gw + 4);            \
    CP_ASYNC16(_dw + 32, _gw + 8);  CP_ASYNC16(_dw + 48, _gw + 12);           \
    CP_COMMIT();                                                              \
} while (0)

    float acc[2][8][4];
#pragma unroll
    for (int i = 0; i < 2; ++i)
#pragma unroll
        for (int j = 0; j < 8; ++j)
#pragma unroll
            for (int r = 0; r < 4; ++r) acc[i][j][r] = 0.f;

    LOAD_CHUNK(0);
    LOAD_CHUNK(1);

#pragma unroll 1
    for (int c = 0; c < NCHUNK; ++c) {
        if (c + 1 < NCHUNK) CP_WAIT1(); else CP_WAIT0();
        __syncthreads();

        const float* Ac = (c & 1) ? As1 : As0;
        const float* Wc = (c & 1) ? Ws1 : Ws0;

#pragma unroll
        for (int ks = 0; ks < 4; ++ks) {
            const int kk = ks * 8 + c4;
            uint32_t a[2][4];
#pragma unroll
            for (int mt = 0; mt < 2; ++mt) {
                const int rm = m_warp + mt * 16 + g8;
                a[mt][0] = f2tf32(Ac[rm * SROW + kk]);
                a[mt][1] = f2tf32(Ac[(rm + 8) * SROW + kk]);
                a[mt][2] = f2tf32(Ac[rm * SROW + kk + 4]);
                a[mt][3] = f2tf32(Ac[(rm + 8) * SROW + kk + 4]);
            }
#pragma unroll
            for (int nt = 0; nt < 8; ++nt) {
                const int rn = n_warp + nt * 8 + g8;
                uint32_t bb0 = f2tf32(Wc[rn * SROW + kk]);
                uint32_t bb1 = f2tf32(Wc[rn * SROW + kk + 4]);
                mma_tf32(acc[0][nt], a[0], bb0, bb1);
                mma_tf32(acc[1][nt], a[1], bb0, bb1);
            }
        }

        __syncthreads();
        if (c + 2 < NCHUNK) LOAD_CHUNK(c + 2);
    }
#undef LOAD_CHUNK

    // epilogue: c0/c1 -> (row, col*2..+1), c2/c3 -> (row+8, same cols)
#pragma unroll
    for (int mt = 0; mt < 2; ++mt) {
        const int row = m0 + m_warp + mt * 16 + g8;
#pragma unroll
        for (int nt = 0; nt < 8; ++nt) {
            const int col = n0 + n_warp + nt * 8 + c4 * 2;
            const float bx = bias[col], by = bias[col + 1];
            float2 r0 = make_float2(acc[mt][nt][0] + bx, acc[mt][nt][1] + by);
            float2 r1 = make_float2(acc[mt][nt][2] + bx, acc[mt][nt][3] + by);
            *(float2*)(Y + (size_t)row * DMODEL + col)       = r0;
            *(float2*)(Y + (size_t)(row + 8) * DMODEL + col) = r1;
        }
    }
}

// ============================================================================
// Causal flash attention (fp32, unchanged from passing baseline).
// ============================================================================
#define AQ 128
#define AK 32

__global__ __launch_bounds__(128)
void attn_kernel(const float* __restrict__ Q, const float* __restrict__ K,
                 const float* __restrict__ V, float* __restrict__ ctx)
{
    __shared__ __align__(16) float Ks[AK][DK];
    __shared__ __align__(16) float Vs[AK][DK];

    const int t  = threadIdx.x;
    const int bq = blockIdx.x;
    const int h  = blockIdx.y;
    const int b  = blockIdx.z;
    const int qg = bq * AQ + t;
    const size_t base = ((size_t)b * TSEQ) * DMODEL + (size_t)h * DK;

    float4 q4[DK / 4];
    {
        const float4* qp = (const float4*)(Q + base + (size_t)qg * DMODEL);
#pragma unroll
        for (int i = 0; i < DK / 4; ++i) {
            float4 v = qp[i];
            v.x *= 0.125f; v.y *= 0.125f; v.z *= 0.125f; v.w *= 0.125f;
            q4[i] = v;
        }
    }

    float4 o4[DK / 4];
#pragma unroll
    for (int i = 0; i < DK / 4; ++i) o4[i] = make_float4(0.f, 0.f, 0.f, 0.f);
    float mrun = -1e30f, lrun = 0.f;

    const int ntiles = bq * (AQ / AK) + (AQ / AK);

    for (int tile = 0; tile < ntiles; ++tile) {
        const int k0 = tile * AK;
        __syncthreads();
#pragma unroll
        for (int it = 0; it < 4; ++it) {
            int idx = it * 128 + t;
            int r = idx >> 4;
            int c = (idx & 15) * 4;
            *(float4*)&Ks[r][c] = *(const float4*)(K + base + (size_t)(k0 + r) * DMODEL + c);
            *(float4*)&Vs[r][c] = *(const float4*)(V + base + (size_t)(k0 + r) * DMODEL + c);
        }
        __syncthreads();

        float s[AK];
        float tmax = -1e30f;
#pragma unroll
        for (int j = 0; j < AK; ++j) {
            float acc = 0.f;
#pragma unroll
            for (int i = 0; i < DK / 4; ++i) {
                float4 kv = *(const float4*)&Ks[j][i * 4];
                acc += q4[i].x * kv.x + q4[i].y * kv.y
                     + q4[i].z * kv.z + q4[i].w * kv.w;
            }
            s[j] = (k0 + j <= qg) ? acc : -1e30f;
            tmax = fmaxf(tmax, s[j]);
        }

        float mnew = fmaxf(mrun, tmax);
        float corr = __expf(mrun - mnew);
        lrun *= corr;
#pragma unroll
        for (int i = 0; i < DK / 4; ++i) {
            o4[i].x *= corr; o4[i].y *= corr; o4[i].z *= corr; o4[i].w *= corr;
        }
#pragma unroll
        for (int j = 0; j < AK; ++j) {
            float p = __expf(s[j] - mnew);
            lrun += p;
#pragma unroll
            for (int i = 0; i < DK / 4; ++i) {
                float4 vv = *(const float4*)&Vs[j][i * 4];
                o4[i].x += p * vv.x; o4[i].y += p * vv.y;
                o4[i].z += p * vv.z; o4[i].w += p * vv.w;
            }
        }
        mrun = mnew;
    }

    const float inv = 1.f / lrun;
    float4* op = (float4*)(ctx + base + (size_t)qg * DMODEL);
#pragma unroll
    for (int i = 0; i < DK / 4; ++i) {
        o4[i].x *= inv; o4[i].y *= inv; o4[i].z *= inv; o4[i].w *= inv;
        op[i] = o4[i];
    }
}

// ============================================================================
// launch
// ============================================================================
extern "C" void kernel_launch(void* const* d_in, const int* in_sizes, int n_in,
                              void* d_out, int out_size)
{
    const float* x  = (const float*)d_in[0];
    const float* Wq = (const float*)d_in[1];
    const float* bq = (const float*)d_in[2];
    const float* Wk = (const float*)d_in[3];
    const float* bk = (const float*)d_in[4];
    const float* Wv = (const float*)d_in[5];
    const float* bv = (const float*)d_in[6];
    const float* Wo = (const float*)d_in[7];
    const float* bo = (const float*)d_in[8];
    float* out = (float*)d_out;

    float *qp, *kp, *vp, *cp;
    cudaGetSymbolAddress((void**)&qp, g_Q);
    cudaGetSymbolAddress((void**)&kp, g_K);
    cudaGetSymbolAddress((void**)&vp, g_V);
    cudaGetSymbolAddress((void**)&cp, g_ctx);

    cudaFuncSetAttribute(gemm_tc_kernel,
                         cudaFuncAttributeMaxDynamicSharedMemorySize, GEMM_SMEM);

    // fused QKV projections: grid.z selects weight set
    dim3 qkv_grid(DMODEL / 128, MTOK / 128, 3);   // (8, 32, 3)
    gemm_tc_kernel<<<qkv_grid, 256, GEMM_SMEM>>>(
        x, Wq, Wk, Wv, bq, bk, bv, qp, kp, vp);

    dim3 agrid(TSEQ / AQ, NHEADS, BDIM);          // (16, 16, 2)
    attn_kernel<<<agrid, 128>>>(qp, kp, vp, cp);

    dim3 o_grid(DMODEL / 128, MTOK / 128, 1);
    gemm_tc_kernel<<<o_grid, 256, GEMM_SMEM>>>(
        cp, Wo, Wo, Wo, bo, bo, bo, out, out, out);
}

// round 8
// speedup vs baseline: 2.9689x; 2.2656x over previous
#include <cuda_runtime.h>
#include <cstdint>
#include <math.h>

#define BDIM 2
#define TSEQ 2048
#define DMODEL 1024
#define NHEADS 16
#define DK 64
#define MTOK (BDIM * TSEQ)   // 4096

// -------- scratch (device globals; no allocation allowed) --------
__device__ float g_Q[MTOK * DMODEL];
__device__ float g_K[MTOK * DMODEL];
__device__ float g_V[MTOK * DMODEL];
__device__ float g_ctx[MTOK * DMODEL];

// ============================================================================
// helpers
// ============================================================================
__device__ __forceinline__ uint32_t smem_u32(const void* p) {
    uint32_t a;
    asm("{ .reg .u64 t; cvta.to.shared.u64 t, %1; cvt.u32.u64 %0, t; }" : "=r"(a) : "l"(p));
    return a;
}

__device__ __forceinline__ uint32_t f2tf32(float f) {
    uint32_t r;
    asm("cvt.rna.tf32.f32 %0, %1;" : "=r"(r) : "f"(f));
    return r;
}

__device__ __forceinline__ void mma_tf32(float* d, const uint32_t* a,
                                         uint32_t b0, uint32_t b1) {
    asm volatile(
        "mma.sync.aligned.m16n8k8.row.col.f32.tf32.tf32.f32 "
        "{%0,%1,%2,%3}, {%4,%5,%6,%7}, {%8,%9}, {%0,%1,%2,%3};"
        : "+f"(d[0]), "+f"(d[1]), "+f"(d[2]), "+f"(d[3])
        : "r"(a[0]), "r"(a[1]), "r"(a[2]), "r"(a[3]), "r"(b0), "r"(b1));
}

#define CP_ASYNC16(dst, src) \
    asm volatile("cp.async.cg.shared.global [%0], [%1], 16;" \
                 :: "r"((uint32_t)(dst)), "l"(src) : "memory")
#define CP_COMMIT() asm volatile("cp.async.commit_group;" ::: "memory")
#define CP_WAIT1()  asm volatile("cp.async.wait_group 1;" ::: "memory")
#define CP_WAIT0()  asm volatile("cp.async.wait_group 0;" ::: "memory")

// ============================================================================
// tf32 mma.sync GEMM (unchanged from R6 passing kernel)
// ============================================================================
#define GBK 32
#define NCHUNK (DMODEL / GBK)      // 32
#define SROW 36
#define TILE_F (128 * SROW)
#define GEMM_SMEM (4 * TILE_F * 4) // 73728 bytes

__global__ __launch_bounds__(256)
void gemm_tc_kernel(const float* __restrict__ A,
                    const float* __restrict__ W0, const float* __restrict__ W1,
                    const float* __restrict__ W2,
                    const float* __restrict__ b0, const float* __restrict__ b1,
                    const float* __restrict__ b2,
                    float* __restrict__ Y0, float* __restrict__ Y1,
                    float* __restrict__ Y2)
{
    extern __shared__ float smem[];
    float* As0 = smem;
    float* Ws0 = As0 + TILE_F;
    float* As1 = Ws0 + TILE_F;
    float* Ws1 = As1 + TILE_F;

    const float* W = W0; const float* bias = b0; float* Y = Y0;
    if (blockIdx.z == 1) { W = W1; bias = b1; Y = Y1; }
    else if (blockIdx.z == 2) { W = W2; bias = b2; Y = Y2; }

    const int tid  = threadIdx.x;
    const int wid  = tid >> 5;
    const int lane = tid & 31;
    const int m0 = blockIdx.y * 128;
    const int n0 = blockIdx.x * 128;

    const int m_warp = (wid & 3) * 32;
    const int n_warp = (wid >> 2) * 64;
    const int c4 = lane & 3;
    const int g8 = lane >> 2;

    const int rowL  = tid >> 1;
    const int khalf = (tid & 1) * 16;

    const float* Abase = A + (size_t)(m0 + rowL) * DMODEL + khalf;
    const float* Wbase = W + (size_t)(n0 + rowL) * DMODEL + khalf;
    const uint32_t sAoff = (uint32_t)(rowL * SROW + khalf) * 4u;
    const uint32_t sA0 = smem_u32(As0) + sAoff;
    const uint32_t sW0 = smem_u32(Ws0) + sAoff;
    const uint32_t sA1 = smem_u32(As1) + sAoff;
    const uint32_t sW1 = smem_u32(Ws1) + sAoff;

#define LOAD_CHUNK(c) do {                                                    \
    uint32_t _da = ((c) & 1) ? sA1 : sA0;                                     \
    uint32_t _dw = ((c) & 1) ? sW1 : sW0;                                     \
    const float* _ga = Abase + (c) * GBK;                                     \
    const float* _gw = Wbase + (c) * GBK;                                     \
    CP_ASYNC16(_da,      _ga);      CP_ASYNC16(_da + 16, _ga + 4);            \
    CP_ASYNC16(_da + 32, _ga + 8);  CP_ASYNC16(_da + 48, _ga + 12);           \
    CP_ASYNC16(_dw,      _gw);      CP_ASYNC16(_dw + 16, _gw + 4);            \
    CP_ASYNC16(_dw + 32, _gw + 8);  CP_ASYNC16(_dw + 48, _gw + 12);           \
    CP_COMMIT();                                                              \
} while (0)

    float acc[2][8][4];
#pragma unroll
    for (int i = 0; i < 2; ++i)
#pragma unroll
        for (int j = 0; j < 8; ++j)
#pragma unroll
            for (int r = 0; r < 4; ++r) acc[i][j][r] = 0.f;

    LOAD_CHUNK(0);
    LOAD_CHUNK(1);

#pragma unroll 1
    for (int c = 0; c < NCHUNK; ++c) {
        if (c + 1 < NCHUNK) CP_WAIT1(); else CP_WAIT0();
        __syncthreads();

        const float* Ac = (c & 1) ? As1 : As0;
        const float* Wc = (c & 1) ? Ws1 : Ws0;

#pragma unroll
        for (int ks = 0; ks < 4; ++ks) {
            const int kk = ks * 8 + c4;
            uint32_t a[2][4];
#pragma unroll
            for (int mt = 0; mt < 2; ++mt) {
                const int rm = m_warp + mt * 16 + g8;
                a[mt][0] = f2tf32(Ac[rm * SROW + kk]);
                a[mt][1] = f2tf32(Ac[(rm + 8) * SROW + kk]);
                a[mt][2] = f2tf32(Ac[rm * SROW + kk + 4]);
                a[mt][3] = f2tf32(Ac[(rm + 8) * SROW + kk + 4]);
            }
#pragma unroll
            for (int nt = 0; nt < 8; ++nt) {
                const int rn = n_warp + nt * 8 + g8;
                uint32_t bb0 = f2tf32(Wc[rn * SROW + kk]);
                uint32_t bb1 = f2tf32(Wc[rn * SROW + kk + 4]);
                mma_tf32(acc[0][nt], a[0], bb0, bb1);
                mma_tf32(acc[1][nt], a[1], bb0, bb1);
            }
        }

        __syncthreads();
        if (c + 2 < NCHUNK) LOAD_CHUNK(c + 2);
    }
#undef LOAD_CHUNK

#pragma unroll
    for (int mt = 0; mt < 2; ++mt) {
        const int row = m0 + m_warp + mt * 16 + g8;
#pragma unroll
        for (int nt = 0; nt < 8; ++nt) {
            const int col = n0 + n_warp + nt * 8 + c4 * 2;
            const float bx = bias[col], by = bias[col + 1];
            float2 r0 = make_float2(acc[mt][nt][0] + bx, acc[mt][nt][1] + by);
            float2 r1 = make_float2(acc[mt][nt][2] + bx, acc[mt][nt][3] + by);
            *(float2*)(Y + (size_t)row * DMODEL + col)       = r0;
            *(float2*)(Y + (size_t)(row + 8) * DMODEL + col) = r1;
        }
    }
}

// ============================================================================
// Tensor-core causal flash attention (tf32 mma.sync).
// 8 warps x 16 q-rows = 128 q/CTA; Bk=32 keys/tile; dk=64.
// K: cp.async double-buffer [32][68] fp32 (cvt on read).
// V: LDG -> transpose+tf32 store into Vt[64][36] (CF banks both directions).
// P: warp-private smem [16][36] tf32 bits (accum layout out, A-frag layout in).
// ============================================================================
#define ABK 32
#define KSTR 68
#define VSTR 36
#define PSTR 36
// smem floats: 2*32*68 + 2*64*36 + 8*16*36 = 4352 + 4608 + 4608 = 13568
#define ATTN_SMEM (13568 * 4)

__global__ __launch_bounds__(256)
void attn_tc_kernel(const float* __restrict__ Q, const float* __restrict__ K,
                    const float* __restrict__ V, float* __restrict__ ctx)
{
    extern __shared__ float sm[];
    float* KsB[2] = { sm, sm + 32 * KSTR };
    uint32_t* VtB[2] = { (uint32_t*)(sm + 2 * 32 * KSTR),
                         (uint32_t*)(sm + 2 * 32 * KSTR + 64 * VSTR) };
    uint32_t* Pw = (uint32_t*)(sm + 2 * 32 * KSTR + 2 * 64 * VSTR);

    const int tid  = threadIdx.x;
    const int wid  = tid >> 5;
    const int lane = tid & 31;
    const int g8 = lane >> 2;
    const int c4 = lane & 3;

    const int bq = blockIdx.x;
    const int h  = blockIdx.y;
    const int b  = blockIdx.z;
    const int wq0 = bq * 128 + wid * 16;                  // warp q base (seq)
    const size_t seqbase = ((size_t)b * TSEQ) * DMODEL + (size_t)h * DK;

    uint32_t* Pme = Pw + wid * 16 * PSTR;

    // ---- Q fragments (tf32, 1/8 scale folded) ----
    uint32_t qa[8][4];
    {
        const float* qlo = Q + seqbase + (size_t)(wq0 + g8) * DMODEL;
        const float* qhi = qlo + 8 * DMODEL;
#pragma unroll
        for (int ks = 0; ks < 8; ++ks) {
            qa[ks][0] = f2tf32(qlo[8 * ks + c4]     * 0.125f);
            qa[ks][1] = f2tf32(qhi[8 * ks + c4]     * 0.125f);
            qa[ks][2] = f2tf32(qlo[8 * ks + c4 + 4] * 0.125f);
            qa[ks][3] = f2tf32(qhi[8 * ks + c4 + 4] * 0.125f);
        }
    }

    const int ntiles = 4 * bq + 4;

    // loader mappings
    const int kkey = tid >> 3, kseg = (tid & 7) * 8;   // K tile: row, 8-float seg
    const int vkey = tid & 31, vseg = (tid >> 5) * 8;  // V tile: row, 8-float seg
    const uint32_t ks0a = smem_u32(KsB[0]) + (uint32_t)(kkey * KSTR + kseg) * 4u;
    const uint32_t ks1a = smem_u32(KsB[1]) + (uint32_t)(kkey * KSTR + kseg) * 4u;

    // ---- prologue: tile0 K cp.async; V0 LDG->STS; tile1 prefetch ----
    {
        const float* kr = K + seqbase + (size_t)kkey * DMODEL + kseg;
        CP_ASYNC16(ks0a, kr); CP_ASYNC16(ks0a + 16, kr + 4);
        CP_COMMIT();
    }
    {
        const float* vr = V + seqbase + (size_t)vkey * DMODEL + vseg;
        float4 a = *(const float4*)vr, c = *(const float4*)(vr + 4);
        uint32_t* Vn = VtB[0];
        Vn[(vseg + 0) * VSTR + vkey] = f2tf32(a.x);
        Vn[(vseg + 1) * VSTR + vkey] = f2tf32(a.y);
        Vn[(vseg + 2) * VSTR + vkey] = f2tf32(a.z);
        Vn[(vseg + 3) * VSTR + vkey] = f2tf32(a.w);
        Vn[(vseg + 4) * VSTR + vkey] = f2tf32(c.x);
        Vn[(vseg + 5) * VSTR + vkey] = f2tf32(c.y);
        Vn[(vseg + 6) * VSTR + vkey] = f2tf32(c.z);
        Vn[(vseg + 7) * VSTR + vkey] = f2tf32(c.w);
    }
    float4 va, vb;   // V(it+1) staged in regs
    {
        const float* kr = K + seqbase + (size_t)(ABK + kkey) * DMODEL + kseg;
        CP_ASYNC16(ks1a, kr); CP_ASYNC16(ks1a + 16, kr + 4);
        CP_COMMIT();
        const float* vr = V + seqbase + (size_t)(ABK + vkey) * DMODEL + vseg;
        va = *(const float4*)vr; vb = *(const float4*)(vr + 4);
    }
    CP_WAIT1();          // K0 landed (K1 still in flight)
    __syncthreads();     // Vt0 + K0 visible

    float m0 = -1e30f, m1 = -1e30f, l0 = 0.f, l1 = 0.f;
    float o[8][4];
#pragma unroll
    for (int nf = 0; nf < 8; ++nf)
#pragma unroll
        for (int r = 0; r < 4; ++r) o[nf][r] = 0.f;

    const int rlo = wq0 + g8, rhi = rlo + 8;

#pragma unroll 1
    for (int it = 0; it < ntiles; ++it) {
        const int k0 = it * ABK;
        const float*    Kc = KsB[it & 1];
        const uint32_t* Vc = VtB[it & 1];

        // prefetch V(it+2) into fresh regs (overlaps compute)
        float4 na, nb;
        const bool have2 = (it + 2 < ntiles);
        if (have2) {
            const float* vr = V + seqbase + (size_t)((it + 2) * ABK + vkey) * DMODEL + vseg;
            na = *(const float4*)vr; nb = *(const float4*)(vr + 4);
        }

        if (k0 <= wq0 + 15) {
            // ---- S = Q K^T ----
            float s[4][4];
#pragma unroll
            for (int nf = 0; nf < 4; ++nf)
#pragma unroll
                for (int r = 0; r < 4; ++r) s[nf][r] = 0.f;
#pragma unroll
            for (int ks = 0; ks < 8; ++ks) {
#pragma unroll
                for (int nf = 0; nf < 4; ++nf) {
                    const float* kp = Kc + (nf * 8 + g8) * KSTR + ks * 8 + c4;
                    uint32_t bb0 = f2tf32(kp[0]);
                    uint32_t bb1 = f2tf32(kp[4]);
                    mma_tf32(s[nf], qa[ks], bb0, bb1);
                }
            }

            // ---- causal mask (diagonal tiles only) ----
            if (k0 + ABK - 1 > wq0) {
#pragma unroll
                for (int nf = 0; nf < 4; ++nf) {
                    const int kg = k0 + nf * 8 + 2 * c4;
                    if (kg     > rlo) s[nf][0] = -1e30f;
                    if (kg + 1 > rlo) s[nf][1] = -1e30f;
                    if (kg     > rhi) s[nf][2] = -1e30f;
                    if (kg + 1 > rhi) s[nf][3] = -1e30f;
                }
            }

            // ---- online softmax ----
            float tl = -1e30f, th = -1e30f;
#pragma unroll
            for (int nf = 0; nf < 4; ++nf) {
                tl = fmaxf(tl, fmaxf(s[nf][0], s[nf][1]));
                th = fmaxf(th, fmaxf(s[nf][2], s[nf][3]));
            }
            tl = fmaxf(tl, __shfl_xor_sync(0xffffffffu, tl, 1));
            tl = fmaxf(tl, __shfl_xor_sync(0xffffffffu, tl, 2));
            th = fmaxf(th, __shfl_xor_sync(0xffffffffu, th, 1));
            th = fmaxf(th, __shfl_xor_sync(0xffffffffu, th, 2));

            const float mn0 = fmaxf(m0, tl), mn1 = fmaxf(m1, th);
            const float cr0 = __expf(m0 - mn0), cr1 = __expf(m1 - mn1);
            float sl = 0.f, sh = 0.f;
#pragma unroll
            for (int nf = 0; nf < 4; ++nf) {
                float p0 = __expf(s[nf][0] - mn0);
                float p1 = __expf(s[nf][1] - mn0);
                float p2 = __expf(s[nf][2] - mn1);
                float p3 = __expf(s[nf][3] - mn1);
                sl += p0 + p1; sh += p2 + p3;
                Pme[g8 * PSTR + nf * 8 + 2 * c4]           = f2tf32(p0);
                Pme[g8 * PSTR + nf * 8 + 2 * c4 + 1]       = f2tf32(p1);
                Pme[(g8 + 8) * PSTR + nf * 8 + 2 * c4]     = f2tf32(p2);
                Pme[(g8 + 8) * PSTR + nf * 8 + 2 * c4 + 1] = f2tf32(p3);
            }
            sl += __shfl_xor_sync(0xffffffffu, sl, 1);
            sl += __shfl_xor_sync(0xffffffffu, sl, 2);
            sh += __shfl_xor_sync(0xffffffffu, sh, 1);
            sh += __shfl_xor_sync(0xffffffffu, sh, 2);
            l0 = l0 * cr0 + sl;  l1 = l1 * cr1 + sh;
            m0 = mn0;  m1 = mn1;
#pragma unroll
            for (int nf = 0; nf < 8; ++nf) {
                o[nf][0] *= cr0; o[nf][1] *= cr0;
                o[nf][2] *= cr1; o[nf][3] *= cr1;
            }
            __syncwarp();

            // ---- O += P V ----
#pragma unroll
            for (int ks = 0; ks < 4; ++ks) {
                uint32_t a[4];
                a[0] = Pme[g8 * PSTR + ks * 8 + c4];
                a[1] = Pme[(g8 + 8) * PSTR + ks * 8 + c4];
                a[2] = Pme[g8 * PSTR + ks * 8 + c4 + 4];
                a[3] = Pme[(g8 + 8) * PSTR + ks * 8 + c4 + 4];
#pragma unroll
                for (int nf = 0; nf < 8; ++nf) {
                    uint32_t bb0 = Vc[(nf * 8 + g8) * VSTR + ks * 8 + c4];
                    uint32_t bb1 = Vc[(nf * 8 + g8) * VSTR + ks * 8 + c4 + 4];
                    mma_tf32(o[nf], a, bb0, bb1);
                }
            }
        }

        // ---- pipeline advance ----
        if (it + 1 < ntiles) {
            CP_WAIT0();          // K(it+1) landed
            __syncthreads();     // all reads of tile(it) buffers done
            uint32_t* Vn = VtB[(it + 1) & 1];
            Vn[(vseg + 0) * VSTR + vkey] = f2tf32(va.x);
            Vn[(vseg + 1) * VSTR + vkey] = f2tf32(va.y);
            Vn[(vseg + 2) * VSTR + vkey] = f2tf32(va.z);
            Vn[(vseg + 3) * VSTR + vkey] = f2tf32(va.w);
            Vn[(vseg + 4) * VSTR + vkey] = f2tf32(vb.x);
            Vn[(vseg + 5) * VSTR + vkey] = f2tf32(vb.y);
            Vn[(vseg + 6) * VSTR + vkey] = f2tf32(vb.z);
            Vn[(vseg + 7) * VSTR + vkey] = f2tf32(vb.w);
            if (have2) {
                const float* kr = K + seqbase + (size_t)((it + 2) * ABK + kkey) * DMODEL + kseg;
                const uint32_t dst = (it & 1) ? ks1a : ks0a;
                CP_ASYNC16(dst, kr); CP_ASYNC16(dst + 16, kr + 4);
                CP_COMMIT();
                va = na; vb = nb;
            }
            __syncthreads();     // Vt(it+1) visible
        }
    }

    // ---- epilogue ----
    const float inv0 = 1.f / l0, inv1 = 1.f / l1;
    float* olo = ctx + seqbase + (size_t)rlo * DMODEL;
    float* ohi = ctx + seqbase + (size_t)rhi * DMODEL;
#pragma unroll
    for (int nf = 0; nf < 8; ++nf) {
        const int col = nf * 8 + 2 * c4;
        *(float2*)(olo + col) = make_float2(o[nf][0] * inv0, o[nf][1] * inv0);
        *(float2*)(ohi + col) = make_float2(o[nf][2] * inv1, o[nf][3] * inv1);
    }
}

// ============================================================================
// launch
// ============================================================================
extern "C" void kernel_launch(void* const* d_in, const int* in_sizes, int n_in,
                              void* d_out, int out_size)
{
    const float* x  = (const float*)d_in[0];
    const float* Wq = (const float*)d_in[1];
    const float* bq = (const float*)d_in[2];
    const float* Wk = (const float*)d_in[3];
    const float* bk = (const float*)d_in[4];
    const float* Wv = (const float*)d_in[5];
    const float* bv = (const float*)d_in[6];
    const float* Wo = (const float*)d_in[7];
    const float* bo = (const float*)d_in[8];
    float* out = (float*)d_out;

    float *qp, *kp, *vp, *cp;
    cudaGetSymbolAddress((void**)&qp, g_Q);
    cudaGetSymbolAddress((void**)&kp, g_K);
    cudaGetSymbolAddress((void**)&vp, g_V);
    cudaGetSymbolAddress((void**)&cp, g_ctx);

    cudaFuncSetAttribute(gemm_tc_kernel,
                         cudaFuncAttributeMaxDynamicSharedMemorySize, GEMM_SMEM);
    cudaFuncSetAttribute(attn_tc_kernel,
                         cudaFuncAttributeMaxDynamicSharedMemorySize, ATTN_SMEM);

    dim3 qkv_grid(DMODEL / 128, MTOK / 128, 3);   // (8, 32, 3)
    gemm_tc_kernel<<<qkv_grid, 256, GEMM_SMEM>>>(
        x, Wq, Wk, Wv, bq, bk, bv, qp, kp, vp);

    dim3 agrid(TSEQ / 128, NHEADS, BDIM);         // (16, 16, 2)
    attn_tc_kernel<<<agrid, 256, ATTN_SMEM>>>(qp, kp, vp, cp);

    dim3 o_grid(DMODEL / 128, MTOK / 128, 1);
    gemm_tc_kernel<<<o_grid, 256, GEMM_SMEM>>>(
        cp, Wo, Wo, Wo, bo, bo, bo, out, out, out);
}